// round 1
// baseline (speedup 1.0000x reference)
#include <cuda_runtime.h>

// SKA_Small: out[b,g,cg,h,w] = sum_{ki,kj in 3x3} x[b,g,cg,h+ki-1,w+kj-1] * w[b,g,ki*3+kj,h,w]
// x:   [B=8, C=64, H=128, W=128] f32   (C = G*Cg = 8*8)
// w:   [B=8, G=8, 1, 9, H=128, W=128] f32
// out: [B=8, C=64, H=128, W=128] f32
//
// Memory-bound (~105 MB min traffic). One thread = one (b,g,h, 4-wide w quad),
// loops all Cg=8 channels so the 9 weight float4s are loaded once and reused 8x.

constexpr int B = 8, C = 64, H = 128, W = 128, G = 8, CG = 8;
constexpr int HW = H * W;

__global__ __launch_bounds__(256) void ska_small_kernel(
    const float* __restrict__ x,
    const float* __restrict__ w,
    float* __restrict__ out)
{
    // total threads = B * G * H * (W/4) = 8*8*128*32 = 262144
    int tid = blockIdx.x * blockDim.x + threadIdx.x;
    int w4 = tid & 31;          // W/4 = 32
    int h  = (tid >> 5) & 127;  // H
    int g  = (tid >> 12) & 7;   // G
    int b  = tid >> 15;         // B
    int w0 = w4 * 4;

    // Load the 9 per-pixel weight vectors (shared across all 8 channels).
    const float* wb = w + (((long)(b * G + g)) * 9) * HW + h * W + w0;
    float4 wk[9];
    #pragma unroll
    for (int k = 0; k < 9; k++)
        wk[k] = *(const float4*)(wb + (long)k * HW);

    const float* xb = x   + (((long)(b * C + g * CG)) * H + h) * W + w0;
    float*       ob = out + (((long)(b * C + g * CG)) * H + h) * W + w0;

    const bool hm = (h > 0);
    const bool hp = (h < H - 1);
    const bool wl = (w0 > 0);
    const bool wr = (w0 + 4 < W);

    #pragma unroll
    for (int cg = 0; cg < CG; cg++) {
        const float* xc = xb + (long)cg * HW;
        float a0 = 0.f, a1 = 0.f, a2 = 0.f, a3 = 0.f;

        #pragma unroll
        for (int ki = 0; ki < 3; ki++) {
            const int dh = ki - 1;
            const bool rv = (dh == 0) | (dh < 0 ? hm : hp);
            const float* row = xc + dh * W;

            float4 c = rv ? *(const float4*)row : make_float4(0.f, 0.f, 0.f, 0.f);
            float  l = (rv & wl) ? row[-1] : 0.f;
            float  r = (rv & wr) ? row[4]  : 0.f;

            const float4 wa = wk[ki * 3 + 0];  // kj=0: x[w-1]
            const float4 wm = wk[ki * 3 + 1];  // kj=1: x[w]
            const float4 wc = wk[ki * 3 + 2];  // kj=2: x[w+1]

            a0 = fmaf(wa.x, l,   fmaf(wm.x, c.x, fmaf(wc.x, c.y, a0)));
            a1 = fmaf(wa.y, c.x, fmaf(wm.y, c.y, fmaf(wc.y, c.z, a1)));
            a2 = fmaf(wa.z, c.y, fmaf(wm.z, c.z, fmaf(wc.z, c.w, a2)));
            a3 = fmaf(wa.w, c.z, fmaf(wm.w, c.w, fmaf(wc.w, r,   a3)));
        }

        *(float4*)(ob + (long)cg * HW) = make_float4(a0, a1, a2, a3);
    }
}

extern "C" void kernel_launch(void* const* d_in, const int* in_sizes, int n_in,
                              void* d_out, int out_size)
{
    const float* x = (const float*)d_in[0];
    const float* w = (const float*)d_in[1];
    float* out = (float*)d_out;

    const int total = B * G * H * (W / 4);  // 262144
    const int threads = 256;
    const int blocks = total / threads;     // 1024
    ska_small_kernel<<<blocks, threads>>>(x, w, out);
}

// round 3
// speedup vs baseline: 1.0180x; 1.0180x over previous
#include <cuda_runtime.h>

// SKA_Small: out[b,g,cg,h,w] = sum_{3x3 taps} x[b,g,cg,h+ki-1,w+kj-1] * w[b,g,ki*3+kj,h,w]
// x:   [8, 64, 128, 128] f32, w: [8, 8, 1, 9, 128, 128] f32, out like x.
//
// R2: latency-bound fix. Thread = (b,g, channel-pair q, h, 4-wide quad).
// 2 channels per thread -> all 19 loads (9 w float4 + 2ch x 5 x-loads)
// are independent and hoisted before the FMAs => high per-warp MLP.
// w re-read by 4 sibling thread-groups; 3 of 4 reads hit L2 (adjacent blocks).

constexpr int B = 8, C = 64, H = 128, W = 128, G = 8, CG = 8;
constexpr int HW = H * W;

__global__ __launch_bounds__(256, 3) void ska_small_kernel(
    const float* __restrict__ x,
    const float* __restrict__ w,
    float* __restrict__ out)
{
    // total threads = (B*G) * 4 * H * (W/4) = 64*4*128*32 = 1048576
    int tid = blockIdx.x * blockDim.x + threadIdx.x;
    int w4 = tid & 31;           // W/4
    int h  = (tid >> 5) & 127;   // H
    int q  = (tid >> 12) & 3;    // channel pair index (channels 2q, 2q+1)
    int bg = tid >> 14;          // b*G + g  (0..63)
    int w0 = w4 * 4;

    // ---- issue ALL loads up front (independent) ----
    const float* wb = w + ((long)bg * 9) * HW + h * W + w0;
    float4 wk[9];
    #pragma unroll
    for (int k = 0; k < 9; k++)
        wk[k] = *(const float4*)(wb + (long)k * HW);

    const bool hm = (h > 0);
    const bool hp = (h < H - 1);
    const bool wl = (w0 > 0);
    const bool wr = (w0 + 4 < W);

    const int c0 = q * 2;
    const float* xb = x + ((long)(bg * CG + c0)) * HW + h * W + w0;

    float4 xc[2][3];
    float  xl[2][3], xr[2][3];
    #pragma unroll
    for (int c = 0; c < 2; c++) {
        const float* xch = xb + (long)c * HW;
        #pragma unroll
        for (int ki = 0; ki < 3; ki++) {
            const int dh = ki - 1;
            const bool rv = (dh == 0) | (dh < 0 ? hm : hp);
            const float* row = xch + dh * W;
            xc[c][ki] = rv ? *(const float4*)row : make_float4(0.f, 0.f, 0.f, 0.f);
            xl[c][ki] = (rv & wl) ? row[-1] : 0.f;
            xr[c][ki] = (rv & wr) ? row[4]  : 0.f;
        }
    }

    // ---- FMAs ----
    float* ob = out + ((long)(bg * CG + c0)) * HW + h * W + w0;
    #pragma unroll
    for (int c = 0; c < 2; c++) {
        float a0 = 0.f, a1 = 0.f, a2 = 0.f, a3 = 0.f;
        #pragma unroll
        for (int ki = 0; ki < 3; ki++) {
            const float4 v  = xc[c][ki];
            const float  l  = xl[c][ki];
            const float  r  = xr[c][ki];
            const float4 wa = wk[ki * 3 + 0];  // tap (ki, 0): x[w-1]
            const float4 wm = wk[ki * 3 + 1];  // tap (ki, 1): x[w]
            const float4 wc = wk[ki * 3 + 2];  // tap (ki, 2): x[w+1]

            a0 = fmaf(wa.x, l,   fmaf(wm.x, v.x, fmaf(wc.x, v.y, a0)));
            a1 = fmaf(wa.y, v.x, fmaf(wm.y, v.y, fmaf(wc.y, v.z, a1)));
            a2 = fmaf(wa.z, v.y, fmaf(wm.z, v.z, fmaf(wc.z, v.w, a2)));
            a3 = fmaf(wa.w, v.z, fmaf(wm.w, v.w, fmaf(wc.w, r,   a3)));
        }
        *(float4*)(ob + (long)c * HW) = make_float4(a0, a1, a2, a3);
    }
}

extern "C" void kernel_launch(void* const* d_in, const int* in_sizes, int n_in,
                              void* d_out, int out_size)
{
    const float* x = (const float*)d_in[0];
    const float* w = (const float*)d_in[1];
    float* out = (float*)d_out;

    const int total = (B * G) * 4 * H * (W / 4);  // 1048576
    const int threads = 256;
    const int blocks = total / threads;           // 4096
    ska_small_kernel<<<blocks, threads>>>(x, w, out);
}

// round 5
// speedup vs baseline: 1.1027x; 1.0832x over previous
#include <cuda_runtime.h>

// SKA_Small: out[b,g,cg,h,w] = sum_{3x3 taps} x[b,g,cg,h+ki-1,w+kj-1] * w[b,g,ki*3+kj,h,w]
// x:   [8, 64, 128, 128] f32, w: [8, 8, 1, 9, 128, 128] f32, out like x.
//
// R3: warp spans exactly one row (32 lanes x float4 = 128 = W), so horizontal
// halos come from neighbor lanes via shfl instead of scalar loads.
// x loads: 6 coalesced float4/thread (was 18 loads). Regs down -> 4 blocks/SM.

constexpr int B = 8, C = 64, H = 128, W = 128, G = 8, CG = 8;
constexpr int HW = H * W;

__global__ __launch_bounds__(256, 4) void ska_small_kernel(
    const float* __restrict__ x,
    const float* __restrict__ w,
    float* __restrict__ out)
{
    // total threads = (B*G) * 4 * H * (W/4) = 1048576
    int tid  = blockIdx.x * blockDim.x + threadIdx.x;
    int lane = threadIdx.x & 31;     // == w4
    int h    = (tid >> 5) & 127;     // H
    int q    = (tid >> 12) & 3;      // channel pair (channels 2q, 2q+1)
    int bg   = tid >> 14;            // b*G + g
    int w0   = lane * 4;

    // ---- hoist all loads (independent) ----
    const float* wb = w + (bg * 9) * HW + h * W + w0;
    float4 wk[9];
    #pragma unroll
    for (int k = 0; k < 9; k++)
        wk[k] = *(const float4*)(wb + k * HW);

    const bool hm = (h > 0);
    const bool hp = (h < H - 1);

    const int c0 = q * 2;
    const float* xb = x + (bg * CG + c0) * HW + h * W + w0;

    float4 xc[2][3];
    #pragma unroll
    for (int c = 0; c < 2; c++) {
        const float* xch = xb + c * HW;
        #pragma unroll
        for (int ki = 0; ki < 3; ki++) {
            const int dh = ki - 1;
            const bool rv = (dh == 0) | (dh < 0 ? hm : hp);
            xc[c][ki] = rv ? *(const float4*)(xch + dh * W)
                           : make_float4(0.f, 0.f, 0.f, 0.f);
        }
    }

    // ---- compute: halos from neighbor lanes via shfl ----
    float* ob = out + (bg * CG + c0) * HW + h * W + w0;
    #pragma unroll
    for (int c = 0; c < 2; c++) {
        float a0 = 0.f, a1 = 0.f, a2 = 0.f, a3 = 0.f;
        #pragma unroll
        for (int ki = 0; ki < 3; ki++) {
            const float4 v = xc[c][ki];
            float l = __shfl_up_sync(0xffffffffu, v.w, 1);
            float r = __shfl_down_sync(0xffffffffu, v.x, 1);
            if (lane == 0)  l = 0.f;   // w0 == 0: left pad
            if (lane == 31) r = 0.f;   // w0+4 == W: right pad

            const float4 wa = wk[ki * 3 + 0];  // tap (ki,0): x[w-1]
            const float4 wm = wk[ki * 3 + 1];  // tap (ki,1): x[w]
            const float4 wc = wk[ki * 3 + 2];  // tap (ki,2): x[w+1]

            a0 = fmaf(wa.x, l,   fmaf(wm.x, v.x, fmaf(wc.x, v.y, a0)));
            a1 = fmaf(wa.y, v.x, fmaf(wm.y, v.y, fmaf(wc.y, v.z, a1)));
            a2 = fmaf(wa.z, v.y, fmaf(wm.z, v.z, fmaf(wc.z, v.w, a2)));
            a3 = fmaf(wa.w, v.z, fmaf(wm.w, v.w, fmaf(wc.w, r,   a3)));
        }
        *(float4*)(ob + c * HW) = make_float4(a0, a1, a2, a3);
    }
}

extern "C" void kernel_launch(void* const* d_in, const int* in_sizes, int n_in,
                              void* d_out, int out_size)
{
    const float* x = (const float*)d_in[0];
    const float* w = (const float*)d_in[1];
    float* out = (float*)d_out;

    const int total = (B * G) * 4 * H * (W / 4);  // 1048576
    ska_small_kernel<<<total / 256, 256>>>(x, w, out);
}

// round 7
// speedup vs baseline: 1.2771x; 1.1581x over previous
#include <cuda_runtime.h>

// SKA_Small: out[b,g,cg,h,w] = sum_{3x3 taps} x[b,g,cg,h+ki-1,w+kj-1] * w[b,g,ki*3+kj,h,w]
// x: [8,64,128,128] f32, w: [8,8,1,9,128,128] f32, out like x.
//
// R4: smem-staged w. Block = (bg, 2 rows, all 8 channels); 8 warps =
// (row hh) x (channel-pair q). w staged to smem once per block (global w
// traffic 1x instead of 4x), read back per-ki so only 12 w regs are live
// -> 5 blocks/SM. x halos via shfl; x loads hoisted before the staging sync.

constexpr int B = 8, C = 64, H = 128, W = 128, G = 8, CG = 8;
constexpr int HW = H * W;

__global__ __launch_bounds__(256, 5) void ska_small_kernel(
    const float* __restrict__ x,
    const float* __restrict__ w,
    float* __restrict__ out)
{
    // smem: [row r:2][tap k:9][lane:32] float4 = 576 float4 = 9216 B
    __shared__ float4 sw[576];

    const int t    = threadIdx.x;
    const int lane = t & 31;
    const int warp = t >> 5;
    const int q    = warp & 3;   // channel pair (channels 2q, 2q+1)
    const int hh   = warp >> 2;  // row within block (0/1)
    const int bg   = blockIdx.x >> 6;         // b*G + g
    const int h0   = (blockIdx.x & 63) << 1;  // first of 2 rows
    const int h    = h0 + hh;
    const int w0   = lane * 4;

    // ---- x loads first (independent of smem staging) ----
    const bool hm = (h > 0);
    const bool hp = (h < H - 1);
    const int  c0 = q * 2;
    const float* xb = x + (bg * CG + c0) * HW + h * W + w0;

    float4 xc[2][3];
    #pragma unroll
    for (int c = 0; c < 2; c++) {
        const float* xch = xb + c * HW;
        #pragma unroll
        for (int ki = 0; ki < 3; ki++) {
            const int dh = ki - 1;
            const bool rv = (dh == 0) | (dh < 0 ? hm : hp);
            xc[c][ki] = rv ? *(const float4*)(xch + dh * W)
                           : make_float4(0.f, 0.f, 0.f, 0.f);
        }
    }

    // ---- cooperative w staging: 576 float4 across 256 threads ----
    #pragma unroll
    for (int i = 0; i < 3; i++) {
        const int f = t + i * 256;
        if (f < 576) {
            const int r   = f / 288;        // row 0/1
            const int rem = f - r * 288;
            const int k   = rem >> 5;       // tap 0..8
            const int pos = rem & 31;       // lane position
            sw[f] = *(const float4*)(w + (bg * 9 + k) * HW + (h0 + r) * W + pos * 4);
        }
    }
    __syncthreads();

    // ---- compute: w from smem per-ki (reused for both channels) ----
    float a00=0.f,a01=0.f,a02=0.f,a03=0.f;
    float a10=0.f,a11=0.f,a12=0.f,a13=0.f;
    const int swb = hh * 288 + lane;

    #pragma unroll
    for (int ki = 0; ki < 3; ki++) {
        const float4 wa = sw[swb + (ki * 3 + 0) * 32];  // tap (ki,0): x[w-1]
        const float4 wm = sw[swb + (ki * 3 + 1) * 32];  // tap (ki,1): x[w]
        const float4 wc = sw[swb + (ki * 3 + 2) * 32];  // tap (ki,2): x[w+1]

        {
            const float4 v = xc[0][ki];
            float l = __shfl_up_sync(0xffffffffu, v.w, 1);
            float r = __shfl_down_sync(0xffffffffu, v.x, 1);
            if (lane == 0)  l = 0.f;
            if (lane == 31) r = 0.f;
            a00 = fmaf(wa.x, l,   fmaf(wm.x, v.x, fmaf(wc.x, v.y, a00)));
            a01 = fmaf(wa.y, v.x, fmaf(wm.y, v.y, fmaf(wc.y, v.z, a01)));
            a02 = fmaf(wa.z, v.y, fmaf(wm.z, v.z, fmaf(wc.z, v.w, a02)));
            a03 = fmaf(wa.w, v.z, fmaf(wm.w, v.w, fmaf(wc.w, r,   a03)));
        }
        {
            const float4 v = xc[1][ki];
            float l = __shfl_up_sync(0xffffffffu, v.w, 1);
            float r = __shfl_down_sync(0xffffffffu, v.x, 1);
            if (lane == 0)  l = 0.f;
            if (lane == 31) r = 0.f;
            a10 = fmaf(wa.x, l,   fmaf(wm.x, v.x, fmaf(wc.x, v.y, a10)));
            a11 = fmaf(wa.y, v.x, fmaf(wm.y, v.y, fmaf(wc.y, v.z, a11)));
            a12 = fmaf(wa.z, v.y, fmaf(wm.z, v.z, fmaf(wc.z, v.w, a12)));
            a13 = fmaf(wa.w, v.z, fmaf(wm.w, v.w, fmaf(wc.w, r,   a13)));
        }
    }

    float* ob = out + (bg * CG + c0) * HW + h * W + w0;
    *(float4*)(ob)      = make_float4(a00, a01, a02, a03);
    *(float4*)(ob + HW) = make_float4(a10, a11, a12, a13);
}

extern "C" void kernel_launch(void* const* d_in, const int* in_sizes, int n_in,
                              void* d_out, int out_size)
{
    const float* x = (const float*)d_in[0];
    const float* w = (const float*)d_in[1];
    float* out = (float*)d_out;

    // blocks: 64 bg * 64 row-pairs = 4096
    ska_small_kernel<<<4096, 256>>>(x, w, out);
}

// round 8
// speedup vs baseline: 1.3188x; 1.0327x over previous
#include <cuda_runtime.h>

// SKA_Small: out[b,g,cg,h,w] = sum_{3x3 taps} x[b,g,cg,h+ki-1,w+kj-1] * w[b,g,ki*3+kj,h,w]
// x: [8,64,128,128] f32, w: [8,8,1,9,128,128] f32, out like x.
//
// R5: one warp = (bg, h), ALL 8 channels. Each w float4 is read from global
// exactly once chip-wide (no smem staging, no syncthreads, no LDS).
// Horizontal halos via lane shuffles; vertical halos via uniform predicates.
// ~26.5 L1 wavefronts per output float4 (was ~49 in R4).

constexpr int B = 8, C = 64, H = 128, W = 128, G = 8, CG = 8;
constexpr int HW = H * W;

__global__ __launch_bounds__(128, 8) void ska_small_kernel(
    const float* __restrict__ x,
    const float* __restrict__ w,
    float* __restrict__ out)
{
    // total threads = (B*G) * H * 32 = 262144 ; block = 128 (4 warps = 4 rows)
    const int tid  = blockIdx.x * 128 + threadIdx.x;
    const int lane = threadIdx.x & 31;
    const int wid  = tid >> 5;        // global warp id
    const int h    = wid & 127;
    const int bg   = wid >> 7;        // b*G + g
    const int w0   = lane * 4;

    // ---- 9 per-pixel weight vectors, resident for all 8 channels ----
    const float* wb = w + (bg * 9) * HW + h * W + w0;
    float4 wk[9];
    #pragma unroll
    for (int k = 0; k < 9; k++)
        wk[k] = *(const float4*)(wb + k * HW);

    const bool hm = (h > 0);
    const bool hp = (h < H - 1);

    const float* xb = x   + (bg * CG) * HW + h * W + w0;
    float*       ob = out + (bg * CG) * HW + h * W + w0;

    #pragma unroll
    for (int c = 0; c < CG; c++) {
        const float* xch = xb + c * HW;

        // load 3 rows (vertical pad via uniform predicates)
        float4 v0 = hm ? *(const float4*)(xch - W) : make_float4(0.f, 0.f, 0.f, 0.f);
        float4 v1 =      *(const float4*)(xch);
        float4 v2 = hp ? *(const float4*)(xch + W) : make_float4(0.f, 0.f, 0.f, 0.f);

        float a0 = 0.f, a1 = 0.f, a2 = 0.f, a3 = 0.f;

        #pragma unroll
        for (int ki = 0; ki < 3; ki++) {
            const float4 v = (ki == 0) ? v0 : (ki == 1) ? v1 : v2;
            float l = __shfl_up_sync(0xffffffffu, v.w, 1);
            float r = __shfl_down_sync(0xffffffffu, v.x, 1);
            if (lane == 0)  l = 0.f;
            if (lane == 31) r = 0.f;

            const float4 wa = wk[ki * 3 + 0];  // tap (ki,0): x[w-1]
            const float4 wm = wk[ki * 3 + 1];  // tap (ki,1): x[w]
            const float4 wc = wk[ki * 3 + 2];  // tap (ki,2): x[w+1]

            a0 = fmaf(wa.x, l,   fmaf(wm.x, v.x, fmaf(wc.x, v.y, a0)));
            a1 = fmaf(wa.y, v.x, fmaf(wm.y, v.y, fmaf(wc.y, v.z, a1)));
            a2 = fmaf(wa.z, v.y, fmaf(wm.z, v.z, fmaf(wc.z, v.w, a2)));
            a3 = fmaf(wa.w, v.z, fmaf(wm.w, v.w, fmaf(wc.w, r,   a3)));
        }

        *(float4*)(ob + c * HW) = make_float4(a0, a1, a2, a3);
    }
}

extern "C" void kernel_launch(void* const* d_in, const int* in_sizes, int n_in,
                              void* d_out, int out_size)
{
    const float* x = (const float*)d_in[0];
    const float* w = (const float*)d_in[1];
    float* out = (float*)d_out;

    const int total = (B * G) * H * 32;  // 262144 threads
    ska_small_kernel<<<total / 128, 128>>>(x, w, out);
}

// round 9
// speedup vs baseline: 1.4133x; 1.0717x over previous
#include <cuda_runtime.h>

// SKA_Small: out[b,g,cg,h,w] = sum_{3x3 taps} x[b,g,cg,h+ki-1,w+kj-1] * w[b,g,ki*3+kj,h,w]
// x: [8,64,128,128] f32, w: [8,8,1,9,128,128] f32, out like x.
//
// R6: one warp = (bg, h) row, all 8 channels (w read once chip-wide), and each
// warp now processes TWO work items via grid stride -> 4096 warps = single
// fully-resident wave (was 1.73 waves). Item-2's 9 w loads overlap item-1's
// tail FMAs/stores. Halos: shfl horizontally, predicates vertically.

constexpr int B = 8, C = 64, H = 128, W = 128, G = 8, CG = 8;
constexpr int HW = H * W;
constexpr int ITEMS = (B * G) * H;        // 8192 warp-rows
constexpr int WARPS = ITEMS / 2;          // 4096 resident warps

__global__ __launch_bounds__(256, 4) void ska_small_kernel(
    const float* __restrict__ x,
    const float* __restrict__ w,
    float* __restrict__ out)
{
    const int lane  = threadIdx.x & 31;
    const int warp0 = (blockIdx.x * 256 + threadIdx.x) >> 5;  // 0..4095
    const int w0    = lane * 4;

    #pragma unroll
    for (int it = 0; it < 2; it++) {
        const int item = warp0 + it * WARPS;   // 0..8191
        const int h    = item & 127;
        const int bg   = item >> 7;            // b*G + g

        // ---- 9 per-pixel weight vectors, resident across all 8 channels ----
        const float* wbp = w + (bg * 9) * HW + h * W + w0;
        float4 wk[9];
        #pragma unroll
        for (int k = 0; k < 9; k++)
            wk[k] = *(const float4*)(wbp + k * HW);

        const bool hm = (h > 0);
        const bool hp = (h < H - 1);

        const float* xb = x   + (bg * CG) * HW + h * W + w0;
        float*       ob = out + (bg * CG) * HW + h * W + w0;

        #pragma unroll
        for (int c = 0; c < CG; c++) {
            const float* xch = xb + c * HW;

            float4 v0 = hm ? *(const float4*)(xch - W) : make_float4(0.f, 0.f, 0.f, 0.f);
            float4 v1 =      *(const float4*)(xch);
            float4 v2 = hp ? *(const float4*)(xch + W) : make_float4(0.f, 0.f, 0.f, 0.f);

            float a0 = 0.f, a1 = 0.f, a2 = 0.f, a3 = 0.f;

            #pragma unroll
            for (int ki = 0; ki < 3; ki++) {
                const float4 v = (ki == 0) ? v0 : (ki == 1) ? v1 : v2;
                float l = __shfl_up_sync(0xffffffffu, v.w, 1);
                float r = __shfl_down_sync(0xffffffffu, v.x, 1);
                if (lane == 0)  l = 0.f;
                if (lane == 31) r = 0.f;

                const float4 wa = wk[ki * 3 + 0];  // tap (ki,0): x[w-1]
                const float4 wm = wk[ki * 3 + 1];  // tap (ki,1): x[w]
                const float4 wc = wk[ki * 3 + 2];  // tap (ki,2): x[w+1]

                a0 = fmaf(wa.x, l,   fmaf(wm.x, v.x, fmaf(wc.x, v.y, a0)));
                a1 = fmaf(wa.y, v.x, fmaf(wm.y, v.y, fmaf(wc.y, v.z, a1)));
                a2 = fmaf(wa.z, v.y, fmaf(wm.z, v.z, fmaf(wc.z, v.w, a2)));
                a3 = fmaf(wa.w, v.z, fmaf(wm.w, v.w, fmaf(wc.w, r,   a3)));
            }

            *(float4*)(ob + c * HW) = make_float4(a0, a1, a2, a3);
        }
    }
}

extern "C" void kernel_launch(void* const* d_in, const int* in_sizes, int n_in,
                              void* d_out, int out_size)
{
    const float* x = (const float*)d_in[0];
    const float* w = (const float*)d_in[1];
    float* out = (float*)d_out;

    // 4096 warps = 512 blocks x 256 threads; 4 blocks/SM -> single wave
    ska_small_kernel<<<WARPS * 32 / 256, 256>>>(x, w, out);
}